// round 15
// baseline (speedup 1.0000x reference)
#include <cuda_runtime.h>

// N = 2^26 FFT of REAL fp32 input via half-length complex FFT (M = 2^25):
//   z[n] = x[2n] + i x[2n+1] (free reinterpret), Z = FFT_M(z), Hermitian unpack.
// Decomposition M = 256 * 512 * 256:
//   P1:  radix-256, s=1      z -> D   (d_out scratch)      [verified r7-r14]
//   P2:  radix-512, s=256    D -> B   (g_buf)              [verified r12-r14]
//   P3U v7: final radix-256 (ps=0) fused with Hermitian unpack, SMALL BLOCKS:
//        256 thr, 8 A-groups + 8 mirror B-groups, 34.8KB smem -> 6 blocks/SM
//        (blocks destagger -> memory/compute overlap). Grid 8193. B -> out.

#define NFFT  (1u << 26)
#define MFFT  (1u << 25)
#define M256  (1u << 17)   // MFFT/256
#define M512  (1u << 16)   // MFFT/512
#define SFIN  (1u << 17)   // final-pass stride s
#define NPAIR3 8193u       // SFIN/8/2 + 1 self-mirror chunk
#define HBV7  2176u        // per-half smem region (float2), stride-136 slots
#define TWO_PI 6.28318530717958647692f
#define INVM  (1.0f / 33554432.0f)
#define INVN  (1.0f / 67108864.0f)

static __device__ float2 g_buf[MFFT];  // 256 MB scratch (sanctioned)

// exp(-2*pi*i*j/256), j = 0..15
__constant__ float2 c_w256[16] = {
    { 1.00000000000000000f, -0.00000000000000000f},
    { 0.99969881869620422f, -0.02454122852291229f},
    { 0.99879545620517241f, -0.04906767432741801f},
    { 0.99729045667869021f, -0.07356456359966743f},
    { 0.99518472667219693f, -0.09801714032956060f},
    { 0.99247953459870997f, -0.12241067519921620f},
    { 0.98917650996478101f, -0.14673047445536175f},
    { 0.98527764238894122f, -0.17096188876030122f},
    { 0.98078528040323044f, -0.19509032201612825f},
    { 0.97570213003852857f, -0.21910124015686980f},
    { 0.97003125319454397f, -0.24298017990326390f},
    { 0.96377606579543984f, -0.26671275747489837f},
    { 0.95694033573220882f, -0.29028467725446233f},
    { 0.94952818059303667f, -0.31368174039889152f},
    { 0.94154406518302081f, -0.33688985339222005f},
    { 0.93299279883473896f, -0.35989503653498817f}
};
// exp(-2*pi*i*k/32), k = 0..15
__constant__ float2 c_w32[16] = {
    { 1.00000000000000000f, -0.00000000000000000f},
    { 0.98078528040323045f, -0.19509032201612827f},
    { 0.92387953251128676f, -0.38268343236508977f},
    { 0.83146961230254524f, -0.55557023301960222f},
    { 0.70710678118654752f, -0.70710678118654752f},
    { 0.55557023301960222f, -0.83146961230254524f},
    { 0.38268343236508977f, -0.92387953251128676f},
    { 0.19509032201612827f, -0.98078528040323045f},
    { 0.00000000000000000f, -1.00000000000000000f},
    {-0.19509032201612827f, -0.98078528040323045f},
    {-0.38268343236508977f, -0.92387953251128676f},
    {-0.55557023301960222f, -0.83146961230254524f},
    {-0.70710678118654752f, -0.70710678118654752f},
    {-0.83146961230254524f, -0.55557023301960222f},
    {-0.92387953251128676f, -0.38268343236508977f},
    {-0.98078528040323045f, -0.19509032201612827f}
};

__device__ __forceinline__ float2 cmul(float2 a, float2 b) {
    return make_float2(a.x * b.x - a.y * b.y, a.x * b.y + a.y * b.x);
}
__device__ __forceinline__ float2 cadd(float2 a, float2 b) {
    return make_float2(a.x + b.x, a.y + b.y);
}
__device__ __forceinline__ float2 csub(float2 a, float2 b) {
    return make_float2(a.x - b.x, a.y - b.y);
}
__device__ __forceinline__ float2 cmul_negi(float2 a) { return make_float2(a.y, -a.x); }
__device__ __forceinline__ float2 cmul_posi(float2 a) { return make_float2(-a.y, a.x); }

// In-place forward DFT-16, natural order in/out (verified rounds 2-14).
__device__ __forceinline__ void dft16(float2 a[16]) {
    const float C1 = 0.92387953251128675613f;
    const float S1 = 0.38268343236508977173f;
    const float H  = 0.70710678118654752440f;
    const float2 W1 = make_float2( C1, -S1);
    const float2 W2 = make_float2(  H,  -H);
    const float2 W3 = make_float2( S1, -C1);
    const float2 W4 = make_float2(0.f, -1.f);
    const float2 W6 = make_float2( -H,  -H);
    const float2 W9 = make_float2(-C1,  S1);
    float2 b[16];
#pragma unroll
    for (int r1 = 0; r1 < 4; ++r1) {
        float2 x0 = a[r1], x1 = a[r1 + 4], x2 = a[r1 + 8], x3 = a[r1 + 12];
        float2 e = cadd(x0, x2), f = csub(x0, x2);
        float2 g = cadd(x1, x3), h = csub(x1, x3);
        b[r1 * 4 + 0] = cadd(e, g);
        b[r1 * 4 + 1] = cadd(f, cmul_negi(h));
        b[r1 * 4 + 2] = csub(e, g);
        b[r1 * 4 + 3] = cadd(f, cmul_posi(h));
    }
    b[5]  = cmul(b[5],  W1);
    b[6]  = cmul(b[6],  W2);
    b[7]  = cmul(b[7],  W3);
    b[9]  = cmul(b[9],  W2);
    b[10] = cmul(b[10], W4);
    b[11] = cmul(b[11], W6);
    b[13] = cmul(b[13], W3);
    b[14] = cmul(b[14], W6);
    b[15] = cmul(b[15], W9);
#pragma unroll
    for (int k1 = 0; k1 < 4; ++k1) {
        float2 x0 = b[k1], x1 = b[4 + k1], x2 = b[8 + k1], x3 = b[12 + k1];
        float2 e = cadd(x0, x2), f = csub(x0, x2);
        float2 g = cadd(x1, x3), h = csub(x1, x3);
        a[k1 + 0]  = cadd(e, g);
        a[k1 + 4]  = cadd(f, cmul_negi(h));
        a[k1 + 8]  = csub(e, g);
        a[k1 + 12] = cadd(f, cmul_posi(h));
    }
}

__device__ __forceinline__ unsigned swz(unsigned l) { return l + (l >> 8); }

// ---------------------------------------------------------------------------
// P1: radix-256, s=1, complex input (verified rounds 7-14, verbatim).
// ---------------------------------------------------------------------------
__global__ void __launch_bounds__(256) fft256_first(const float2* __restrict__ x,
                                                    float2* __restrict__ y) {
    __shared__ float2 sm[4112];
    unsigned tid = threadIdx.x;
    unsigned g = tid & 15u, j2 = tid >> 4;
    unsigned t = blockIdx.x * 16u + g;

    float2 a[16];
#pragma unroll
    for (int i = 0; i < 16; ++i) a[i] = x[t + (16u * (unsigned)i + j2) * M256];
    dft16(a);

    float sn, cs;
    __sincosf(-TWO_PI * (float)t * INVM, &sn, &cs);
    float2 wg = make_float2(cs, sn);
    float2 w1 = cmul(c_w256[j2], wg);
    float2 w = make_float2(1.f, 0.f);
#pragma unroll
    for (int k1 = 0; k1 < 16; ++k1) {
        sm[swz(tid + 256u * (unsigned)k1)] = cmul(a[k1], w);
        w = cmul(w, w1);
    }
    __syncthreads();

    unsigned k1p = tid >> 4;
#pragma unroll
    for (int j = 0; j < 16; ++j)
        a[j] = sm[swz(256u * k1p + 16u * (unsigned)j + g)];
    dft16(a);

    float2 w2 = cmul(wg, wg);
    w2 = cmul(w2, w2); w2 = cmul(w2, w2); w2 = cmul(w2, w2);  // wg^16
    float2 r[16];
    w = make_float2(1.f, 0.f);
#pragma unroll
    for (int k2 = 0; k2 < 16; ++k2) { r[k2] = cmul(a[k2], w); w = cmul(w, w2); }

    __syncthreads();
#pragma unroll
    for (int k2 = 0; k2 < 16; ++k2)
        sm[swz(256u * g + k1p + 16u * (unsigned)k2)] = r[k2];
    __syncthreads();

    unsigned base = blockIdx.x * 4096u;
#pragma unroll
    for (int i = 0; i < 16; ++i) {
        unsigned m = tid + 256u * (unsigned)i;
        y[base + m] = sm[swz(m)];
    }
}

// ---------------------------------------------------------------------------
// P2: radix-512 mid stage, s=256 (verified rounds 12-14, verbatim).
// ---------------------------------------------------------------------------
#define GS3 513u
__global__ void __launch_bounds__(512) fft512_mid(const float2* __restrict__ x,
                                                  float2* __restrict__ y) {
    extern __shared__ float2 smd[];
    const unsigned tid = threadIdx.x;
    const unsigned g = tid & 15u, u = tid >> 4;   // u in [0,32)
    const unsigned t = blockIdx.x * 16u + g;      // t in [0, 2^16)
    const unsigned gb = g * GS3;

    float2 a[16];
#pragma unroll
    for (int j = 0; j < 16; ++j) a[j] = x[t + (u + 32u * (unsigned)j) * M512];

    dft16(a);
    {
        float sn, cs;
        __sincosf(-TWO_PI * (float)u * (1.0f / 512.0f), &sn, &cs);
        float2 wa = make_float2(cs, sn), w = make_float2(1.f, 0.f);
#pragma unroll
        for (int k = 0; k < 16; ++k) {
            smd[gb + 16u * u + (unsigned)k] = cmul(a[k], w);
            w = cmul(w, wa);
        }
    }
    __syncthreads();

#pragma unroll
    for (int j = 0; j < 16; ++j) a[j] = smd[gb + u + 32u * (unsigned)j];
    dft16(a);
    __syncthreads();
    {
        unsigned q15 = u & 15u, p = u >> 4;
#pragma unroll
        for (int k = 0; k < 16; ++k) {
            float2 v = (p == 0u) ? a[k] : cmul(a[k], c_w32[k]);
            smd[gb + q15 + 256u * p + 16u * (unsigned)k] = v;
        }
    }
    __syncthreads();

    const unsigned q = t & 255u;
    const unsigned ps = t - q;
    const float fps = (float)ps;
    float2 Wu, W32, W256;
    { float sn, cs; __sincosf(-TWO_PI * (fps * (float)u) * INVM, &sn, &cs); Wu   = make_float2(cs, sn); }
    { float sn, cs; __sincosf(-TWO_PI * (fps * 32.0f) * INVM, &sn, &cs);    W32  = make_float2(cs, sn); }
    { float sn, cs; __sincosf(-TWO_PI * (fps * 256.0f) * INVM, &sn, &cs);   W256 = make_float2(cs, sn); }

    const unsigned base = q + (ps << 9);
    float2 w = Wu;
#pragma unroll
    for (int i = 0; i < 8; ++i) {
        unsigned t2 = u + 32u * (unsigned)i;
        float2 b0 = smd[gb + t2];
        float2 b1 = smd[gb + t2 + 256u];
        float2 v0 = cadd(b0, b1);
        float2 v1 = csub(b0, b1);
        y[base + (t2 << 8)]           = cmul(v0, w);
        y[base + ((t2 + 256u) << 8)]  = cmul(v1, cmul(w, W256));
        w = cmul(w, W32);
    }
}

// ---------------------------------------------------------------------------
// P3U v7: final radix-256 (ps=0) fused with Hermitian unpack, small blocks.
// 256 thr: half = tid>>7, ltid = tid&127, g = ltid&7, j2 = ltid>>3 in [0,16).
//   tA = 8b + g;  tB = (SFIN - 8b - 7 + g) mod SFIN (group 7-g mirrors g).
// Load a[i] = x[t + (16i + j2)*SFIN] (4x64B chunks/warp), dft16 over i,
// twiddle w256^{j2 k1}, staging slot addr = (g + 8 j2) + 136 k1  [32-bank ok],
// sync, phase-2 read (g + 8 j2') + 136 k1p, dft16 over j2', sync,
// Z addr = g + 8 (k&15) + 136 (k>>4), sync, unpack (r12-verified algebra):
//   gA = tid&7, uu = tid>>3 in [0,32), k = uu + 32j (j<8), mirror kp = 255-k
//   (or (256-k)&255 at t=0), W = e^{-2pi i m/N}, Winc = e^{-2pi i/16}.
// Grid 8193 (last block = self-mirror chunk; duplicates are identical writes).
// ---------------------------------------------------------------------------
__global__ void __launch_bounds__(256) fft256_unpack_v7(
        const float2* __restrict__ x, float* __restrict__ out) {
    extern __shared__ float2 sm[];
    const unsigned tid = threadIdx.x;
    const unsigned bb = blockIdx.x;
    const unsigned half = tid >> 7;
    const unsigned ltid = tid & 127u;
    const unsigned g = ltid & 7u, j2 = ltid >> 3;  // j2 in [0,16)
    const unsigned tA = 8u * bb + g;
    const unsigned tB = (SFIN - 8u * bb - 7u + g) & (SFIN - 1u);
    const unsigned t = half ? tB : tA;
    float2* hb = sm + half * HBV7;

    // ---- load + layer 1 (registers; no smem before this) ----
    float2 a[16];
#pragma unroll
    for (int i = 0; i < 16; ++i) a[i] = x[t + (16u * (unsigned)i + j2) * SFIN];
    dft16(a);
    {
        float2 w1 = c_w256[j2], w = make_float2(1.f, 0.f);
#pragma unroll
        for (int k1 = 0; k1 < 16; ++k1) {
            hb[(g + 8u * j2) + 136u * (unsigned)k1] = cmul(a[k1], w);
            w = cmul(w, w1);
        }
    }
    __syncthreads();

    // ---- layer 2: role k1p = j2 ----
    const unsigned k1p = j2;
#pragma unroll
    for (int j = 0; j < 16; ++j)
        a[j] = hb[(g + 8u * (unsigned)j) + 136u * k1p];
    dft16(a);
    __syncthreads();  // staging reads done before Z overwrite (same region)

    // Z[k1p + 16 k2] at addr g + 8*k1p + 136*k2
#pragma unroll
    for (int k2 = 0; k2 < 16; ++k2)
        hb[g + 8u * k1p + 136u * (unsigned)k2] = a[k2];
    __syncthreads();  // Z visible across halves for unpack

    // ---- unpack (r12-verified algebra) ----
    {
        const unsigned gA = tid & 7u;
        const unsigned uu = tid >> 3;            // [0, 32)
        const unsigned t3 = 8u * bb + gA;        // A-group t (< SFIN)
        const float2* zA = sm + gA;              // + 8*(k&15) + 136*(k>>4)
        const float2* zB = sm + HBV7 + (7u - gA);
        const bool tzero = (t3 == 0u);

        float sn, cs;
        __sincosf(-TWO_PI * (float)(t3 + uu * SFIN) * INVN, &sn, &cs);
        float2 W = make_float2(cs, sn);
        const float2 Winc = c_w32[2];            // e^{-2pi i/16}: k += 32 step

#pragma unroll
        for (int j = 0; j < 8; ++j) {
            unsigned k = uu + 32u * (unsigned)j;
            float2 Zk = zA[8u * (k & 15u) + 136u * (k >> 4)];
            unsigned kp = tzero ? ((256u - k) & 255u) : (255u - k);
            float2 Zm = zB[8u * (kp & 15u) + 136u * (kp >> 4)];

            float2 A = make_float2(0.5f * (Zk.x + Zm.x), 0.5f * (Zk.y - Zm.y));
            float2 C = make_float2(0.5f * (Zk.x - Zm.x), 0.5f * (Zk.y + Zm.y));
            float2 B = make_float2(C.y, -C.x);
            float2 WB = cmul(W, B);
            float2 P = cadd(A, WB);
            float2 Q = csub(A, WB);

            unsigned m = t3 + k * SFIN;              // [0, M)
            unsigned i3 = (NFFT - m) & (NFFT - 1u);  // N - m (mod N)
            unsigned i2 = MFFT - m;
            unsigned i4 = MFFT + m;

            out[m]  = P.x;   out[NFFT + m]  = P.y;
            out[i3] = P.x;   out[NFFT + i3] = -P.y;
            out[i2] = Q.x;   out[NFFT + i2] = -Q.y;
            out[i4] = Q.x;   out[NFFT + i4] = Q.y;

            W = cmul(W, Winc);
        }
    }
}

// ---------------------------------------------------------------------------
// Schedule: P1: z -> D (d_out scratch); P2: D -> B (g_buf); P3U: B -> out.
// P3U reads only g_buf, writes only d_out: no aliasing hazard.
// ---------------------------------------------------------------------------
extern "C" void kernel_launch(void* const* d_in, const int* in_sizes, int n_in,
                              void* d_out, int out_size) {
    const float2* z = (const float2*)d_in[0];   // N reals = M complex (free pack)
    float* out = (float*)d_out;
    float2* D = (float2*)d_out;                 // M float2 scratch fits in out
    float2* B = nullptr;
    cudaGetSymbolAddress((void**)&B, g_buf);

    const size_t smem2 = (size_t)(16u * GS3) * sizeof(float2);   // 65,664 B
    const size_t smem3 = (size_t)(2u * HBV7) * sizeof(float2);   // 34,816 B
    cudaFuncSetAttribute(fft512_mid,
                         cudaFuncAttributeMaxDynamicSharedMemorySize, (int)smem2);
    cudaFuncSetAttribute(fft256_unpack_v7,
                         cudaFuncAttributeMaxDynamicSharedMemorySize, (int)smem3);

    fft256_first    <<<M256 / 16u, 256>>>(z, D);            // 8192 blocks
    fft512_mid      <<<M512 / 16u, 512, smem2>>>(D, B);     // 4096 blocks
    fft256_unpack_v7<<<NPAIR3, 256, smem3>>>(B, out);       // 8193 blocks
}

// round 16
// speedup vs baseline: 1.2268x; 1.2268x over previous
#include <cuda_runtime.h>

// N = 2^26 FFT of REAL fp32 input via half-length complex FFT (M = 2^25):
//   z[n] = x[2n] + i x[2n+1] (free reinterpret), Z = FFT_M(z), Hermitian unpack.
// UNFUSED schedule (fused design closed after 7 failed variants):
//   P1: radix-256, s=1        z   -> D    (d_out scratch)   [verified r7-r15]
//   P2: radix-512, s=256      D   -> Blo  (g_buf lo)        [verified r12-r15]
//   P3: radix-256 FINAL, ps=0 Blo -> Bhi  (g_buf hi)        [r12 body, ps=0]
//   U:  Hermitian unpack      Bhi -> out                    [verified r7]
// All global accesses use streaming cache hints (__ldcs/__stcs).

#define NFFT  (1u << 26)
#define MFFT  (1u << 25)
#define M256  (1u << 17)   // MFFT/256
#define M512  (1u << 16)   // MFFT/512
#define SFIN  (1u << 17)   // final-pass stride s = M/256
#define MHALF (1u << 24)
#define TWO_PI 6.28318530717958647692f
#define INVM  (1.0f / 33554432.0f)
#define INVN  (1.0f / 67108864.0f)

static __device__ float2 g_buf[NFFT];  // 512 MB scratch (sanctioned)

// exp(-2*pi*i*j/256), j = 0..15
__constant__ float2 c_w256[16] = {
    { 1.00000000000000000f, -0.00000000000000000f},
    { 0.99969881869620422f, -0.02454122852291229f},
    { 0.99879545620517241f, -0.04906767432741801f},
    { 0.99729045667869021f, -0.07356456359966743f},
    { 0.99518472667219693f, -0.09801714032956060f},
    { 0.99247953459870997f, -0.12241067519921620f},
    { 0.98917650996478101f, -0.14673047445536175f},
    { 0.98527764238894122f, -0.17096188876030122f},
    { 0.98078528040323044f, -0.19509032201612825f},
    { 0.97570213003852857f, -0.21910124015686980f},
    { 0.97003125319454397f, -0.24298017990326390f},
    { 0.96377606579543984f, -0.26671275747489837f},
    { 0.95694033573220882f, -0.29028467725446233f},
    { 0.94952818059303667f, -0.31368174039889152f},
    { 0.94154406518302081f, -0.33688985339222005f},
    { 0.93299279883473896f, -0.35989503653498817f}
};
// exp(-2*pi*i*k/32), k = 0..15
__constant__ float2 c_w32[16] = {
    { 1.00000000000000000f, -0.00000000000000000f},
    { 0.98078528040323045f, -0.19509032201612827f},
    { 0.92387953251128676f, -0.38268343236508977f},
    { 0.83146961230254524f, -0.55557023301960222f},
    { 0.70710678118654752f, -0.70710678118654752f},
    { 0.55557023301960222f, -0.83146961230254524f},
    { 0.38268343236508977f, -0.92387953251128676f},
    { 0.19509032201612827f, -0.98078528040323045f},
    { 0.00000000000000000f, -1.00000000000000000f},
    {-0.19509032201612827f, -0.98078528040323045f},
    {-0.38268343236508977f, -0.92387953251128676f},
    {-0.55557023301960222f, -0.83146961230254524f},
    {-0.70710678118654752f, -0.70710678118654752f},
    {-0.83146961230254524f, -0.55557023301960222f},
    {-0.92387953251128676f, -0.38268343236508977f},
    {-0.98078528040323045f, -0.19509032201612827f}
};

__device__ __forceinline__ float2 cmul(float2 a, float2 b) {
    return make_float2(a.x * b.x - a.y * b.y, a.x * b.y + a.y * b.x);
}
__device__ __forceinline__ float2 cadd(float2 a, float2 b) {
    return make_float2(a.x + b.x, a.y + b.y);
}
__device__ __forceinline__ float2 csub(float2 a, float2 b) {
    return make_float2(a.x - b.x, a.y - b.y);
}
__device__ __forceinline__ float2 cmul_negi(float2 a) { return make_float2(a.y, -a.x); }
__device__ __forceinline__ float2 cmul_posi(float2 a) { return make_float2(-a.y, a.x); }

// In-place forward DFT-16, natural order in/out (verified rounds 2-15).
__device__ __forceinline__ void dft16(float2 a[16]) {
    const float C1 = 0.92387953251128675613f;
    const float S1 = 0.38268343236508977173f;
    const float H  = 0.70710678118654752440f;
    const float2 W1 = make_float2( C1, -S1);
    const float2 W2 = make_float2(  H,  -H);
    const float2 W3 = make_float2( S1, -C1);
    const float2 W4 = make_float2(0.f, -1.f);
    const float2 W6 = make_float2( -H,  -H);
    const float2 W9 = make_float2(-C1,  S1);
    float2 b[16];
#pragma unroll
    for (int r1 = 0; r1 < 4; ++r1) {
        float2 x0 = a[r1], x1 = a[r1 + 4], x2 = a[r1 + 8], x3 = a[r1 + 12];
        float2 e = cadd(x0, x2), f = csub(x0, x2);
        float2 g = cadd(x1, x3), h = csub(x1, x3);
        b[r1 * 4 + 0] = cadd(e, g);
        b[r1 * 4 + 1] = cadd(f, cmul_negi(h));
        b[r1 * 4 + 2] = csub(e, g);
        b[r1 * 4 + 3] = cadd(f, cmul_posi(h));
    }
    b[5]  = cmul(b[5],  W1);
    b[6]  = cmul(b[6],  W2);
    b[7]  = cmul(b[7],  W3);
    b[9]  = cmul(b[9],  W2);
    b[10] = cmul(b[10], W4);
    b[11] = cmul(b[11], W6);
    b[13] = cmul(b[13], W3);
    b[14] = cmul(b[14], W6);
    b[15] = cmul(b[15], W9);
#pragma unroll
    for (int k1 = 0; k1 < 4; ++k1) {
        float2 x0 = b[k1], x1 = b[4 + k1], x2 = b[8 + k1], x3 = b[12 + k1];
        float2 e = cadd(x0, x2), f = csub(x0, x2);
        float2 g = cadd(x1, x3), h = csub(x1, x3);
        a[k1 + 0]  = cadd(e, g);
        a[k1 + 4]  = cadd(f, cmul_negi(h));
        a[k1 + 8]  = csub(e, g);
        a[k1 + 12] = cadd(f, cmul_posi(h));
    }
}

__device__ __forceinline__ unsigned swz(unsigned l) { return l + (l >> 8); }

// ---------------------------------------------------------------------------
// P1: radix-256, s=1, complex input (verified body + streaming hints).
// ---------------------------------------------------------------------------
__global__ void __launch_bounds__(256) fft256_first(const float2* __restrict__ x,
                                                    float2* __restrict__ y) {
    __shared__ float2 sm[4112];
    unsigned tid = threadIdx.x;
    unsigned g = tid & 15u, j2 = tid >> 4;
    unsigned t = blockIdx.x * 16u + g;

    float2 a[16];
#pragma unroll
    for (int i = 0; i < 16; ++i)
        a[i] = __ldcs(&x[t + (16u * (unsigned)i + j2) * M256]);
    dft16(a);

    float sn, cs;
    __sincosf(-TWO_PI * (float)t * INVM, &sn, &cs);
    float2 wg = make_float2(cs, sn);
    float2 w1 = cmul(c_w256[j2], wg);
    float2 w = make_float2(1.f, 0.f);
#pragma unroll
    for (int k1 = 0; k1 < 16; ++k1) {
        sm[swz(tid + 256u * (unsigned)k1)] = cmul(a[k1], w);
        w = cmul(w, w1);
    }
    __syncthreads();

    unsigned k1p = tid >> 4;
#pragma unroll
    for (int j = 0; j < 16; ++j)
        a[j] = sm[swz(256u * k1p + 16u * (unsigned)j + g)];
    dft16(a);

    float2 w2 = cmul(wg, wg);
    w2 = cmul(w2, w2); w2 = cmul(w2, w2); w2 = cmul(w2, w2);  // wg^16
    float2 r[16];
    w = make_float2(1.f, 0.f);
#pragma unroll
    for (int k2 = 0; k2 < 16; ++k2) { r[k2] = cmul(a[k2], w); w = cmul(w, w2); }

    __syncthreads();
#pragma unroll
    for (int k2 = 0; k2 < 16; ++k2)
        sm[swz(256u * g + k1p + 16u * (unsigned)k2)] = r[k2];
    __syncthreads();

    unsigned base = blockIdx.x * 4096u;
#pragma unroll
    for (int i = 0; i < 16; ++i) {
        unsigned m = tid + 256u * (unsigned)i;
        __stcs(&y[base + m], sm[swz(m)]);
    }
}

// ---------------------------------------------------------------------------
// P2: radix-512 mid stage, s=256 (verified r12-r15 body + streaming hints).
// ---------------------------------------------------------------------------
#define GS3 513u
__global__ void __launch_bounds__(512) fft512_mid(const float2* __restrict__ x,
                                                  float2* __restrict__ y) {
    extern __shared__ float2 smd[];
    const unsigned tid = threadIdx.x;
    const unsigned g = tid & 15u, u = tid >> 4;   // u in [0,32)
    const unsigned t = blockIdx.x * 16u + g;      // t in [0, 2^16)
    const unsigned gb = g * GS3;

    float2 a[16];
#pragma unroll
    for (int j = 0; j < 16; ++j)
        a[j] = __ldcs(&x[t + (u + 32u * (unsigned)j) * M512]);

    dft16(a);
    {
        float sn, cs;
        __sincosf(-TWO_PI * (float)u * (1.0f / 512.0f), &sn, &cs);
        float2 wa = make_float2(cs, sn), w = make_float2(1.f, 0.f);
#pragma unroll
        for (int k = 0; k < 16; ++k) {
            smd[gb + 16u * u + (unsigned)k] = cmul(a[k], w);
            w = cmul(w, wa);
        }
    }
    __syncthreads();

#pragma unroll
    for (int j = 0; j < 16; ++j) a[j] = smd[gb + u + 32u * (unsigned)j];
    dft16(a);
    __syncthreads();
    {
        unsigned q15 = u & 15u, p = u >> 4;
#pragma unroll
        for (int k = 0; k < 16; ++k) {
            float2 v = (p == 0u) ? a[k] : cmul(a[k], c_w32[k]);
            smd[gb + q15 + 256u * p + 16u * (unsigned)k] = v;
        }
    }
    __syncthreads();

    const unsigned q = t & 255u;
    const unsigned ps = t - q;
    const float fps = (float)ps;
    float2 Wu, W32, W256;
    { float sn, cs; __sincosf(-TWO_PI * (fps * (float)u) * INVM, &sn, &cs); Wu   = make_float2(cs, sn); }
    { float sn, cs; __sincosf(-TWO_PI * (fps * 32.0f) * INVM, &sn, &cs);    W32  = make_float2(cs, sn); }
    { float sn, cs; __sincosf(-TWO_PI * (fps * 256.0f) * INVM, &sn, &cs);   W256 = make_float2(cs, sn); }

    const unsigned base = q + (ps << 9);
    float2 w = Wu;
#pragma unroll
    for (int i = 0; i < 8; ++i) {
        unsigned t2 = u + 32u * (unsigned)i;
        float2 b0 = smd[gb + t2];
        float2 b1 = smd[gb + t2 + 256u];
        float2 v0 = cadd(b0, b1);
        float2 v1 = csub(b0, b1);
        __stcs(&y[base + (t2 << 8)],          cmul(v0, w));
        __stcs(&y[base + ((t2 + 256u) << 8)], cmul(v1, cmul(w, W256)));
        w = cmul(w, W32);
    }
}

// ---------------------------------------------------------------------------
// P3: FINAL radix-256, s=2^17 (ps=0 => outer twiddles = 1). Body = verified
// fft256_mid specialized to wg=1. Load a[i]=x[t+(16i+j2)*SFIN]; store
// Z[t + (k1p + 16 k2)*SFIN] (16 consecutive t per index -> 128B chunks).
// ---------------------------------------------------------------------------
__global__ void __launch_bounds__(256) fft256_last(const float2* __restrict__ x,
                                                   float2* __restrict__ y) {
    __shared__ float2 sm[4112];
    unsigned tid = threadIdx.x;
    unsigned g = tid & 15u, j2 = tid >> 4;
    unsigned t = blockIdx.x * 16u + g;   // t in [0, SFIN)

    float2 a[16];
#pragma unroll
    for (int i = 0; i < 16; ++i)
        a[i] = __ldcs(&x[t + (16u * (unsigned)i + j2) * SFIN]);
    dft16(a);
    {
        float2 w1 = c_w256[j2], w = make_float2(1.f, 0.f);
#pragma unroll
        for (int k1 = 0; k1 < 16; ++k1) {
            sm[swz(tid + 256u * (unsigned)k1)] = cmul(a[k1], w);
            w = cmul(w, w1);
        }
    }
    __syncthreads();

    unsigned k1p = tid >> 4;
#pragma unroll
    for (int j = 0; j < 16; ++j)
        a[j] = sm[swz(256u * k1p + 16u * (unsigned)j + g)];
    dft16(a);

    // ps = 0: w2 = 1, store directly. k = k1p + 16 k2.
    const unsigned base = t + k1p * SFIN;
#pragma unroll
    for (int k2 = 0; k2 < 16; ++k2)
        __stcs(&y[base + ((unsigned)k2 << 21)], a[k2]);  // 16*SFIN = 2^21
}

// ---------------------------------------------------------------------------
// U: Hermitian unpack (verified r7 body + streaming hints). Thread k in
// [0, M/2): P = A + W B, Q = A - W B; X[k]=P, X[M-k]=conj Q, X[N-k]=conj P,
// X[M+k]=Q. k=0 handles fixed points X[M/2], X[N-M/2].
// ---------------------------------------------------------------------------
__global__ void __launch_bounds__(256) unpack(const float2* __restrict__ Z,
                                              float* __restrict__ out) {
    unsigned k = blockIdx.x * 256u + threadIdx.x;  // [0, 2^24)
    float2 Zk = __ldcs(&Z[k]);
    float2 Zm = __ldcs(&Z[(MFFT - k) & (MFFT - 1u)]);

    float2 A = make_float2(0.5f * (Zk.x + Zm.x), 0.5f * (Zk.y - Zm.y));
    float2 C = make_float2(0.5f * (Zk.x - Zm.x), 0.5f * (Zk.y + Zm.y));
    float2 B = make_float2(C.y, -C.x);

    float sn, cs;
    __sincosf(-TWO_PI * (float)k * INVN, &sn, &cs);
    float2 WB = cmul(make_float2(cs, sn), B);
    float2 P = cadd(A, WB);
    float2 Q = csub(A, WB);

    __stcs(&out[k], P.x);            __stcs(&out[NFFT + k], P.y);
    __stcs(&out[MFFT - k], Q.x);     __stcs(&out[NFFT + MFFT - k], -Q.y);
    if (k != 0u) {
        __stcs(&out[NFFT - k], P.x);        __stcs(&out[2u * NFFT - k], -P.y);
        __stcs(&out[MFFT + k], Q.x);        __stcs(&out[NFFT + MFFT + k], Q.y);
    } else {
        float2 Zh = __ldcs(&Z[MHALF]);
        __stcs(&out[MHALF], Zh.x);            __stcs(&out[NFFT + MHALF], -Zh.y);
        __stcs(&out[NFFT - MHALF], Zh.x);     __stcs(&out[NFFT + NFFT - MHALF], Zh.y);
    }
}

// ---------------------------------------------------------------------------
// Schedule: P1: z -> D (d_out scratch); P2: D -> Blo; P3: Blo -> Bhi;
//           U: Bhi -> out (planar d_out). U never reads d_out: hazard-free.
// ---------------------------------------------------------------------------
extern "C" void kernel_launch(void* const* d_in, const int* in_sizes, int n_in,
                              void* d_out, int out_size) {
    const float2* z = (const float2*)d_in[0];   // N reals = M complex (free pack)
    float* out = (float*)d_out;
    float2* D = (float2*)d_out;                 // M float2 scratch fits in out
    float2* Bbase = nullptr;
    cudaGetSymbolAddress((void**)&Bbase, g_buf);
    float2* Blo = Bbase;
    float2* Bhi = Bbase + MFFT;

    const size_t smem2 = (size_t)(16u * GS3) * sizeof(float2);  // 65,664 B
    cudaFuncSetAttribute(fft512_mid,
                         cudaFuncAttributeMaxDynamicSharedMemorySize, (int)smem2);

    fft256_first<<<M256 / 16u, 256>>>(z, D);           // 8192 blocks
    fft512_mid  <<<M512 / 16u, 512, smem2>>>(D, Blo);  // 4096 blocks
    fft256_last <<<SFIN / 16u, 256>>>(Blo, Bhi);       // 8192 blocks
    unpack      <<<MHALF / 256u, 256>>>(Bhi, out);     // 65536 blocks
}